// round 2
// baseline (speedup 1.0000x reference)
#include <cuda_runtime.h>

#define FULLMASK 0xffffffffu

constexpr int B = 64;
constexpr int L = 512;
constexpr int R = 1024;
constexpr int A = 14;
constexpr float EPSV = 1e-12f;
constexpr float CUT2 = 25.0f;   // CUTOFF^2

// -------- scratch (device globals; no allocations allowed) --------
__device__ float g_lig_num[B];
__device__ float g_lig_den[B];
__device__ float g_lig_se[B];
__device__ float g_lig_cnt[B];
__device__ float g_acc[4];   // 0: sc_dist_sum, 1: sc_dist_cnt, 2: sc_mse_num, 3: sc_mse_den

// upper-triangle pair table for A=14, packed (i<<4)|j, 91 valid + pad
__device__ const unsigned char d_pairs[96] = {
    0x01,0x02,0x03,0x04,0x05,0x06,0x07,0x08,0x09,0x0A,0x0B,0x0C,0x0D,
    0x12,0x13,0x14,0x15,0x16,0x17,0x18,0x19,0x1A,0x1B,0x1C,0x1D,
    0x23,0x24,0x25,0x26,0x27,0x28,0x29,0x2A,0x2B,0x2C,0x2D,
    0x34,0x35,0x36,0x37,0x38,0x39,0x3A,0x3B,0x3C,0x3D,
    0x45,0x46,0x47,0x48,0x49,0x4A,0x4B,0x4C,0x4D,
    0x56,0x57,0x58,0x59,0x5A,0x5B,0x5C,0x5D,
    0x67,0x68,0x69,0x6A,0x6B,0x6C,0x6D,
    0x78,0x79,0x7A,0x7B,0x7C,0x7D,
    0x89,0x8A,0x8B,0x8C,0x8D,
    0x9A,0x9B,0x9C,0x9D,
    0xAB,0xAC,0xAD,
    0xBC,0xBD,
    0xCD,
    0,0,0,0,0
};

__device__ __forceinline__ float fast_sqrt(float x) {
    float r;
    asm("sqrt.approx.f32 %0, %1;" : "=f"(r) : "f"(x));
    return r;
}

__global__ void zero_kernel() {
    int t = threadIdx.x;
    if (t < B) {
        g_lig_num[t] = 0.f; g_lig_den[t] = 0.f;
        g_lig_se[t]  = 0.f; g_lig_cnt[t] = 0.f;
    }
    if (t < 4) g_acc[t] = 0.f;
}

// ---------------- ligand: coord loss + pairwise distance loss ----------------
// grid = B*8 blocks, 256 threads. Block = (batch b, tile of 64 i-rows).
// Round-robin pairing: unordered pairs (i, (i+k) mod 512), k=1..255 all i,
// k=256 only for i<256 -> each unordered pair exactly once, uniform load.
__global__ void __launch_bounds__(256) ligand_kernel(
    const float* __restrict__ pred, const float* __restrict__ tgt,
    const unsigned int* __restrict__ mask)   // bool serialized as 32-bit words
{
    __shared__ float4 sp[L];   // xyz + |x|^2
    __shared__ float4 st[L];
    __shared__ float  sm[L];

    const int b = blockIdx.x >> 3;
    const int tile = blockIdx.x & 7;
    const float* P = pred + (size_t)b * L * 3;
    const float* T = tgt  + (size_t)b * L * 3;
    const unsigned int* M = mask + (size_t)b * L;
    const int t = threadIdx.x;

    for (int j = t; j < L; j += 256) {
        float px = P[j*3+0], py = P[j*3+1], pz = P[j*3+2];
        float tx = T[j*3+0], ty = T[j*3+1], tz = T[j*3+2];
        sp[j] = make_float4(px, py, pz, px*px + py*py + pz*pz);
        st[j] = make_float4(tx, ty, tz, tx*tx + ty*ty + tz*tz);
        sm[j] = (M[j] != 0u) ? 1.f : 0.f;   // works for int32 and float32 bools
    }
    __syncthreads();

    const int i   = tile * 64 + (t & 63);
    const int off = t >> 6;                 // 0..3
    const float4 pi = sp[i];
    const float4 ti = st[i];
    const float  mi = sm[i];

    float num = 0.f, den = 0.f;
    #pragma unroll 4
    for (int k = 1 + off; k <= 256; k += 4) {
        if (k == 256 && i >= 256) break;    // k=256 pairs counted once (i<256)
        int j = (i + k) & (L - 1);
        float4 pj = sp[j], tj = st[j];
        float  mj = sm[j];
        float dp = pi.x*pj.x; dp = fmaf(pi.y, pj.y, dp); dp = fmaf(pi.z, pj.z, dp);
        float dt = ti.x*tj.x; dt = fmaf(ti.y, tj.y, dt); dt = fmaf(ti.z, tj.z, dt);
        float psq = fmaf(-2.f, dp, pi.w + pj.w);
        float tsq = fmaf(-2.f, dt, ti.w + tj.w);
        float w = (tsq > 0.f && tsq <= CUT2) ? mi * mj : 0.f;
        float pe = fmaxf(psq, EPSV);
        float te = fmaxf(tsq, EPSV);
        float v  = pe + te - 2.f * fast_sqrt(pe * te);   // (pd - td)^2
        num = fmaf(w, v, num);
        den += w;
    }

    // per-batch coordinate MSE (each row handled by its off==0 thread)
    float se = 0.f, cnt = 0.f;
    if (off == 0) {
        float dx = pi.x - ti.x, dy = pi.y - ti.y, dz = pi.z - ti.z;
        se  = mi * (dx*dx + dy*dy + dz*dz);
        cnt = mi;
    }

    const int lane = t & 31;
    #pragma unroll
    for (int s = 16; s > 0; s >>= 1) {
        num += __shfl_down_sync(FULLMASK, num, s);
        den += __shfl_down_sync(FULLMASK, den, s);
        se  += __shfl_down_sync(FULLMASK, se,  s);
        cnt += __shfl_down_sync(FULLMASK, cnt, s);
    }
    __shared__ float4 wr[8];
    if (lane == 0) wr[t >> 5] = make_float4(num, den, se, cnt);
    __syncthreads();
    if (t < 8) {
        float4 v4 = wr[t];
        float a0 = v4.x, a1 = v4.y, a2 = v4.z, a3 = v4.w;
        #pragma unroll
        for (int s = 4; s > 0; s >>= 1) {
            a0 += __shfl_down_sync(0xffu, a0, s);
            a1 += __shfl_down_sync(0xffu, a1, s);
            a2 += __shfl_down_sync(0xffu, a2, s);
            a3 += __shfl_down_sync(0xffu, a3, s);
        }
        if (t == 0) {
            atomicAdd(&g_lig_num[b], a0);
            atomicAdd(&g_lig_den[b], a1);
            atomicAdd(&g_lig_se[b],  a2);
            atomicAdd(&g_lig_cnt[b], a3);
        }
    }
}

// ---------------- sidechain: per-residue dist loss + global atom MSE ----------------
// one warp per (b,r) group of 14 atoms; 8 groups per 256-thread block
__global__ void __launch_bounds__(256) sidechain_kernel(
    const float* __restrict__ pred, const float* __restrict__ tgt,
    const unsigned int* __restrict__ mask)   // bool serialized as 32-bit words
{
    __shared__ float sp[8][64];   // [atom*4 + comp], comp 3 = |x|^2
    __shared__ float st[8][64];
    __shared__ float sm[8][16];
    __shared__ float bacc[4];

    const int t = threadIdx.x;
    if (t < 4) bacc[t] = 0.f;
    const int w = t >> 5, lane = t & 31;
    const unsigned int g = blockIdx.x * 8 + w;     // group id < B*R
    const float* P = pred + (size_t)g * (A * 3);
    const float* T = tgt  + (size_t)g * (A * 3);
    float* spw = sp[w];
    float* stw = st[w];

    for (int k = lane; k < A * 3; k += 32) {
        int a = k / 3, c = k - a * 3;
        spw[a * 4 + c] = P[k];
        stw[a * 4 + c] = T[k];
    }
    __syncwarp();
    if (lane < A) {
        float x = spw[lane*4], y = spw[lane*4+1], z = spw[lane*4+2];
        spw[lane*4+3] = x*x + y*y + z*z;
        x = stw[lane*4]; y = stw[lane*4+1]; z = stw[lane*4+2];
        stw[lane*4+3] = x*x + y*y + z*z;
        sm[w][lane] = (mask[(size_t)g * A + lane] != 0u) ? 1.f : 0.f;
    }
    __syncwarp();

    const float4* sp4 = (const float4*)spw;
    const float4* st4 = (const float4*)stw;
    float num = 0.f, den = 0.f;
    #pragma unroll
    for (int it = 0; it < 3; ++it) {
        int p = lane + it * 32;
        if (p < 91) {
            int code = d_pairs[p];
            int i = code >> 4, j = code & 15;
            float4 pi = sp4[i], pj = sp4[j];
            float4 ti = st4[i], tj = st4[j];
            float dp = pi.x*pj.x; dp = fmaf(pi.y, pj.y, dp); dp = fmaf(pi.z, pj.z, dp);
            float dt = ti.x*tj.x; dt = fmaf(ti.y, tj.y, dt); dt = fmaf(ti.z, tj.z, dt);
            float psq = fmaf(-2.f, dp, pi.w + pj.w);
            float tsq = fmaf(-2.f, dt, ti.w + tj.w);
            float ww = (tsq > 0.f && tsq <= CUT2) ? sm[w][i] * sm[w][j] : 0.f;
            float pe = fmaxf(psq, EPSV), te = fmaxf(tsq, EPSV);
            float v = pe + te - 2.f * fast_sqrt(pe * te);
            num = fmaf(ww, v, num);
            den += ww;
        }
    }

    // per-atom MSE (mean over 3 coords)
    float mnum = 0.f, mden = 0.f;
    if (lane < A) {
        float dx = spw[lane*4]   - stw[lane*4];
        float dy = spw[lane*4+1] - stw[lane*4+1];
        float dz = spw[lane*4+2] - stw[lane*4+2];
        float m = sm[w][lane];
        mnum = m * (dx*dx + dy*dy + dz*dz) * (1.f / 3.f);
        mden = m;
    }

    #pragma unroll
    for (int s = 16; s > 0; s >>= 1) {
        num  += __shfl_down_sync(FULLMASK, num,  s);
        den  += __shfl_down_sync(FULLMASK, den,  s);
        mnum += __shfl_down_sync(FULLMASK, mnum, s);
        mden += __shfl_down_sync(FULLMASK, mden, s);
    }

    __syncthreads();   // orders bacc zeroing before warp atomics
    if (lane == 0) {
        float gs = 0.f, gc = 0.f;
        if (den > 0.f) { gs = num / den; gc = 1.f; }  // den>=1 when >0 -> max(den,1)=den
        atomicAdd(&bacc[0], gs);
        atomicAdd(&bacc[1], gc);
        atomicAdd(&bacc[2], mnum);
        atomicAdd(&bacc[3], mden);
    }
    __syncthreads();
    if (t < 4) atomicAdd(&g_acc[t], bacc[t]);
}

// ---------------- finalize ----------------
__global__ void finalize_kernel(float* out, int out_size) {
    const int t = threadIdx.x;   // 64 threads
    float lig = g_lig_se[t] / (3.f * fmaxf(g_lig_cnt[t], 1.f));
    float den = g_lig_den[t];
    float has = den > 0.f ? 1.f : 0.f;
    float ld  = (den > 0.f) ? g_lig_num[t] / den : 0.f;

    const int lane = t & 31;
    #pragma unroll
    for (int s = 16; s > 0; s >>= 1) {
        lig += __shfl_down_sync(FULLMASK, lig, s);
        ld  += __shfl_down_sync(FULLMASK, ld,  s);
        has += __shfl_down_sync(FULLMASK, has, s);
    }
    __shared__ float sh[3][2];
    if (lane == 0) { sh[0][t>>5] = lig; sh[1][t>>5] = ld; sh[2][t>>5] = has; }
    __syncthreads();
    if (t == 0) {
        float ligand_loss = (sh[0][0] + sh[0][1]) / 64.f;
        float hs = sh[2][0] + sh[2][1];
        float ligand_dist = (sh[1][0] + sh[1][1]) / fmaxf(hs, 1.f);
        float sc  = g_acc[2] / fmaxf(g_acc[3], 1.f);
        float scd = g_acc[0] / fmaxf(g_acc[1], 1.f);
        float total = ligand_loss + 0.2f * ligand_dist + 0.5f * sc + 0.1f * scd;
        for (int k = 0; k < out_size; ++k) out[k] = total;
    }
}

extern "C" void kernel_launch(void* const* d_in, const int* in_sizes, int n_in,
                              void* d_out, int out_size) {
    const float* lp  = (const float*)d_in[0];
    const float* lt  = (const float*)d_in[1];
    const float* scp = (const float*)d_in[2];
    const float* sct = (const float*)d_in[3];
    const unsigned int* lm = (const unsigned int*)d_in[4];
    const unsigned int* am = (const unsigned int*)d_in[5];
    (void)in_sizes; (void)n_in;

    zero_kernel<<<1, 64>>>();
    ligand_kernel<<<B * 8, 256>>>(lp, lt, lm);
    sidechain_kernel<<<(B * R) / 8, 256>>>(scp, sct, am);
    finalize_kernel<<<1, 64>>>((float*)d_out, out_size);
}